// round 16
// baseline (speedup 1.0000x reference)
#include <cuda_runtime.h>
#include <cstdint>

#define BLK 256
#define WPC 8
#define CTAS_PER_SM 3
#define GRID_CTAS (148 * CTAS_PER_SM)    /* 444; nwarps = 3552 (mult of 4) */
#define MAX_PARTIALS 8192

#define BUF_BYTES  4032                   /* per row buffer (>= 4016, 16B mult) */
#define COPY_BYTES 4016                   /* ceil4(h2+1001)*4 == 4016 for all h2 */
#define MBAR_REGION 128                   /* 16 barriers x 8B */
#define SMEM_TOTAL (MBAR_REGION + WPC * 2 * BUF_BYTES)   /* 64640 */

#define LOG2E 1.44269504088896340736f
#define LN2   0.69314718055994530942f

__device__ float g_partials[MAX_PARTIALS];
__device__ int   g_done = 0;

__device__ __forceinline__ float ex2f(float x) {
    float r; asm("ex2.approx.ftz.f32 %0, %1;" : "=f"(r) : "f"(x)); return r;
}
__device__ __forceinline__ float lg2f(float x) {
    float r; asm("lg2.approx.ftz.f32 %0, %1;" : "=f"(r) : "f"(x)); return r;
}

__device__ __forceinline__ uint32_t smem_u32(const void* p) {
    uint32_t a;
    asm("{ .reg .u64 t; cvta.to.shared.u64 t, %1; cvt.u32.u64 %0, t; }"
        : "=r"(a) : "l"(p));
    return a;
}

__device__ __forceinline__ void mbar_init(uint32_t a, uint32_t cnt) {
    asm volatile("mbarrier.init.shared.b64 [%0], %1;" :: "r"(a), "r"(cnt) : "memory");
}
__device__ __forceinline__ void mbar_expect(uint32_t a, uint32_t bytes) {
    asm volatile("mbarrier.arrive.expect_tx.shared.b64 _, [%0], %1;"
                 :: "r"(a), "r"(bytes) : "memory");
}
__device__ __forceinline__ void mbar_wait(uint32_t a, uint32_t ph) {
    asm volatile(
        "{\n\t.reg .pred p;\n\t"
        "WAIT_%=:\n\t"
        "mbarrier.try_wait.parity.shared.b64 p, [%0], %1;\n\t"
        "@!p bra WAIT_%=;\n\t}"
        :: "r"(a), "r"(ph) : "memory");
}
__device__ __forceinline__ void fence_async() {
    asm volatile("fence.proxy.async.shared::cta;" ::: "memory");
}
__device__ __forceinline__ void bulk_g2s(uint32_t dst, const void* src,
                                         uint32_t bytes, uint32_t mbar) {
    asm volatile(
        "cp.async.bulk.shared::cluster.global.mbarrier::complete_tx::bytes "
        "[%0], [%1], %2, [%3];"
        :: "r"(dst), "l"(src), "r"(bytes), "r"(mbar) : "memory");
}

__inline__ __device__ float warp_sum(float v) {
    #pragma unroll
    for (int o = 16; o > 0; o >>= 1)
        v += __shfl_xor_sync(0xFFFFFFFFu, v, o);
    return v;
}

// accumulate one float4: e = exp(v) = 2^(v*log2e), l = log2(1 + e*K)
__device__ __forceinline__ void acc4(const float4 q, const float K,
                                     float& se, float& sl)
{
    const float e0 = ex2f(q.x * LOG2E);
    const float e1 = ex2f(q.y * LOG2E);
    const float e2 = ex2f(q.z * LOG2E);
    const float e3 = ex2f(q.w * LOG2E);
    const float l0 = lg2f(fmaf(e0, K, 1.0f));
    const float l1 = lg2f(fmaf(e1, K, 1.0f));
    const float l2 = lg2f(fmaf(e2, K, 1.0f));
    const float l3 = lg2f(fmaf(e3, K, 1.0f));
    se += (e0 + e1) + (e2 + e3);
    sl = fmaf(e0, l0, sl);
    sl = fmaf(e1, l1, sl);
    sl = fmaf(e2, l2, sl);
    sl = fmaf(e3, l3, sl);
}

__device__ __forceinline__ void acc1(const float v, const float K,
                                     float& se, float& sl)
{
    const float e = ex2f(v * LOG2E);
    const float l = lg2f(fmaf(e, K, 1.0f));
    se += e;
    sl = fmaf(e, l, sl);
}

// compute one row resident in shared memory; geometry constant per warp
__device__ __forceinline__ float row_from_smem(
    const float* __restrict__ fs, int h2, int head, int tail, int nrem, int lane)
{
    const float extra = fs[h2 + 1000];
    const float K = ex2f(-extra * LOG2E);

    const float* frow = fs + h2;
    const float4* f4p = (const float4*)(frow + head);

    float se = 0.0f, sl = 0.0f;

    if (lane < head) acc1(frow[lane], K, se, sl);

    acc4(f4p[lane        ], K, se, sl);
    acc4(f4p[lane +  32  ], K, se, sl);
    acc4(f4p[lane +  64  ], K, se, sl);
    acc4(f4p[lane +  96  ], K, se, sl);
    acc4(f4p[lane + 128  ], K, se, sl);
    acc4(f4p[lane + 160  ], K, se, sl);
    acc4(f4p[lane + 192  ], K, se, sl);
    if (lane < nrem) acc4(f4p[lane + 224], K, se, sl);

    if (lane < tail) acc1(frow[1000 - tail + lane], K, se, sl);

    se = warp_sum(se);
    sl = warp_sum(sl);
    return __fdividef(sl, se);
}

// Persistent kernel, one row per warp, rows streamed through SMEM by
// cp.async.bulk with a per-warp 2-deep double buffer (mbarrier completion).
__global__ __launch_bounds__(BLK) void loss_kernel(
    const float* __restrict__ in, int C, int B, float* __restrict__ out)
{
    extern __shared__ unsigned char smem_raw[];

    const int t    = threadIdx.x;
    const int lane = t & 31;
    const int wid  = t >> 5;
    const int warp_gid = blockIdx.x * WPC + wid;
    const int nwarps   = gridDim.x * WPC;

    __shared__ float sh_row[WPC];

    float rowacc = 0.0f;

    if (C == 1000 && (nwarps & 3) == 0) {
        // ---- TMA double-buffered fast path ----
        const uint32_t smem_base = smem_u32(smem_raw);
        const uint32_t mb0 = smem_base + wid * 16;
        const uint32_t mb1 = mb0 + 8;
        const uint32_t sb0 = smem_base + MBAR_REGION + (wid * 2    ) * BUF_BYTES;
        const uint32_t sb1 = smem_base + MBAR_REGION + (wid * 2 + 1) * BUF_BYTES;
        const float* fs0 = (const float*)(smem_raw + MBAR_REGION + (wid * 2    ) * BUF_BYTES);
        const float* fs1 = (const float*)(smem_raw + MBAR_REGION + (wid * 2 + 1) * BUF_BYTES);

        // per-warp invariant geometry: stride 3552*1001 ≡ 0 (mod 4)
        const int h2   = warp_gid & 3;            // S mod 4
        const int head = (4 - h2) & 3;
        const int body = 1000 - head;
        const int tail = body & 3;
        const int nrem = (body >> 2) - 224;       // 25 or 26

        const int nr = (warp_gid < B) ? ((B - warp_gid + nwarps - 1) / nwarps) : 0;

        const char*  src0 = (const char*)(in + (size_t)warp_gid * 1001u - (size_t)h2);
        const size_t dsrc = (size_t)nwarps * 1001u * 4u;   // bytes per row step

        if (lane == 0) {
            mbar_init(mb0, 1);
            mbar_init(mb1, 1);
            fence_async();
        }
        __syncwarp();

        if (lane == 0) {
            if (nr > 0) { mbar_expect(mb0, COPY_BYTES); bulk_g2s(sb0, src0,        COPY_BYTES, mb0); }
            if (nr > 1) { mbar_expect(mb1, COPY_BYTES); bulk_g2s(sb1, src0 + dsrc, COPY_BYTES, mb1); }
        }

        uint32_t ph0 = 0, ph1 = 0;
        int i = 0;
        while (i < nr) {
            // buffer 0
            mbar_wait(mb0, ph0); ph0 ^= 1;
            rowacc += row_from_smem(fs0, h2, head, tail, nrem, lane);
            __syncwarp();
            if (i + 2 < nr && lane == 0) {
                fence_async();
                mbar_expect(mb0, COPY_BYTES);
                bulk_g2s(sb0, src0 + (size_t)(i + 2) * dsrc, COPY_BYTES, mb0);
            }
            i++;
            if (i >= nr) break;
            // buffer 1
            mbar_wait(mb1, ph1); ph1 ^= 1;
            rowacc += row_from_smem(fs1, h2, head, tail, nrem, lane);
            __syncwarp();
            if (i + 2 < nr && lane == 0) {
                fence_async();
                mbar_expect(mb1, COPY_BYTES);
                bulk_g2s(sb1, src0 + (size_t)(i + 2) * dsrc, COPY_BYTES, mb1);
            }
            i++;
        }
    } else {
        // ---- generic fallback (any C): direct LDG ----
        for (int row = warp_gid; row < B; row += nwarps) {
            const size_t S = (size_t)row * (size_t)(C + 1);
            const float K = ex2f(-__ldg(in + S + C) * LOG2E);
            const size_t A = (S + 3) & ~(size_t)3;
            const int head = (int)(A - S);
            const float4* fp4 = (const float4*)(in + A);
            const int body = (int)((size_t)(S + C) - A);
            const int n4 = body >> 2;
            const int tail = body & 3;
            const int nfull = n4 >> 5;

            float se = 0.0f, sl = 0.0f;
            if (lane < head) acc1(__ldg(in + S + lane), K, se, sl);
            #pragma unroll 4
            for (int k = 0; k < nfull; k++)
                acc4(__ldg(fp4 + (k << 5) + lane), K, se, sl);
            const int i = (nfull << 5) + lane;
            if (i < n4) acc4(__ldg(fp4 + i), K, se, sl);
            if (lane < tail) acc1(__ldg(in + S + C - tail + lane), K, se, sl);

            se = warp_sum(se);
            sl = warp_sum(sl);
            rowacc += __fdividef(sl, se);
        }
    }

    if (lane == 0) sh_row[wid] = rowacc;
    __syncthreads();

    __shared__ bool is_last;
    if (t == 0) {
        float part = 0.0f;
        #pragma unroll
        for (int i = 0; i < WPC; i++) part += sh_row[i];
        g_partials[blockIdx.x] = part;
        __threadfence();
        is_last = (atomicAdd(&g_done, 1) == (int)gridDim.x - 1);
    }
    __syncthreads();

    if (is_last) {
        const int nP = gridDim.x;
        float s = 0.0f;
        for (int i = t; i < nP; i += BLK) s += g_partials[i];
        s = warp_sum(s);
        __shared__ float sh_fin[BLK / 32];
        if (lane == 0) sh_fin[t >> 5] = s;
        __syncthreads();
        if (t == 0) {
            float tot = 0.0f;
            #pragma unroll
            for (int i = 0; i < BLK / 32; i++) tot += sh_fin[i];
            out[0] = tot * (LN2 / (float)B);
            g_done = 0;   // reset for next graph replay
        }
    }
}

extern "C" void kernel_launch(void* const* d_in, const int* in_sizes, int n_in,
                              void* d_out, int out_size)
{
    const float* input = (const float*)d_in[0];
    const int B = in_sizes[1];             // target has B elements
    const int C = in_sizes[0] / B - 1;     // logits per row (row stride C+1)
    float* out = (float*)d_out;

    static int smem_set = 0;
    if (!smem_set) {
        cudaFuncSetAttribute(loss_kernel,
                             cudaFuncAttributeMaxDynamicSharedMemorySize,
                             SMEM_TOTAL);
        smem_set = 1;
    }

    loss_kernel<<<GRID_CTAS, BLK, SMEM_TOTAL>>>(input, C, B, out);
}